// round 8
// baseline (speedup 1.0000x reference)
#include <cuda_runtime.h>
#include <cstdint>

#define SEQ   2048
#define DH    128
#define BQ    64
#define BK    32
#define NBH   64
#define NKT   (SEQ / BK)     // 64
#define KPAD  132
#define VPAD  136
#define PPAD  36
#define KBUF  (BK * KPAD)    // 4224 floats
#define VBUF  (BK * VPAD)    // 4352 floats
#define PBUF  (4 * 16 * PPAD)// 2304 floats
#define KS_OFF 0
#define VS_OFF (2 * KBUF)
#define PS_OFF (VS_OFF + 2 * VBUF)
#define L_OFF  (PS_OFF + 2 * PBUF)
#define SMEM_FLOATS (L_OFF + 64)
#define SMEM_BYTES (SMEM_FLOATS * 4)   // 87552 B -> 2 CTAs/SM

__device__ float g_Qs[(size_t)NBH * SEQ * DH];   // tf32, pre-scaled
__device__ float g_Kr[(size_t)NBH * SEQ * DH];   // tf32
__device__ float g_Vr[(size_t)NBH * SEQ * DH];   // tf32

__device__ __forceinline__ float tf32r(float x) {
    uint32_t u; asm("cvt.rna.tf32.f32 %0, %1;" : "=r"(u) : "f"(x));
    return __uint_as_float(u);
}
__device__ __forceinline__ uint32_t smem_u32(const void* p) {
    uint32_t a;
    asm("{ .reg .u64 t; cvta.to.shared.u64 t, %1; cvt.u32.u64 %0, t; }" : "=r"(a) : "l"(p));
    return a;
}
__device__ __forceinline__ void cp16(uint32_t dst, const void* src) {
    asm volatile("cp.async.cg.shared.global [%0], [%1], 16;" :: "r"(dst), "l"(src) : "memory");
}
#define CP_COMMIT() asm volatile("cp.async.commit_group;" ::: "memory")
#define CP_WAIT1()  asm volatile("cp.async.wait_group 1;" ::: "memory")
#define CP_WAIT0()  asm volatile("cp.async.wait_group 0;" ::: "memory")

__device__ __forceinline__ void mma_tf32(float c[4],
                                         uint32_t a0, uint32_t a1, uint32_t a2, uint32_t a3,
                                         uint32_t b0, uint32_t b1) {
    asm volatile(
        "mma.sync.aligned.m16n8k8.row.col.f32.tf32.tf32.f32 "
        "{%0,%1,%2,%3}, {%4,%5,%6,%7}, {%8,%9}, {%0,%1,%2,%3};"
        : "+f"(c[0]), "+f"(c[1]), "+f"(c[2]), "+f"(c[3])
        : "r"(a0), "r"(a1), "r"(a2), "r"(a3), "r"(b0), "r"(b1));
}

__global__ void prep_all(const float* __restrict__ q, const float* __restrict__ k,
                         const float* __restrict__ v) {
    const float sc = 0.08838834764831845f;   // 1/sqrt(128)
    size_t i = (size_t)blockIdx.x * blockDim.x + threadIdx.x;
    float4 a = ((const float4*)q)[i];
    float4 b = ((const float4*)k)[i];
    float4 c = ((const float4*)v)[i];
    a.x = tf32r(a.x * sc); a.y = tf32r(a.y * sc); a.z = tf32r(a.z * sc); a.w = tf32r(a.w * sc);
    b.x = tf32r(b.x); b.y = tf32r(b.y); b.z = tf32r(b.z); b.w = tf32r(b.w);
    c.x = tf32r(c.x); c.y = tf32r(c.y); c.z = tf32r(c.z); c.w = tf32r(c.w);
    ((float4*)g_Qs)[i] = a;
    ((float4*)g_Kr)[i] = b;
    ((float4*)g_Vr)[i] = c;
}

// K tile kt -> buffer buf : 32 rows x 32 float4 = 1024 chunks / 256 thr
__device__ __forceinline__ void load_K(uint32_t sb, int tid, size_t base, int kt, int buf) {
    const float* kg = g_Kr + base + (size_t)kt * BK * DH;
#pragma unroll
    for (int it = 0; it < 4; it++) {
        int idx = tid + it * 256;
        int n = idx >> 5, c = idx & 31;
        cp16(sb + (uint32_t)(KS_OFF + buf * KBUF + n * KPAD + 4 * c) * 4u,
             kg + (size_t)n * DH + 4 * c);
    }
}
__device__ __forceinline__ void load_V(uint32_t sb, int tid, size_t base, int kt, int buf) {
    const float* vg = g_Vr + base + (size_t)kt * BK * DH;
#pragma unroll
    for (int it = 0; it < 4; it++) {
        int idx = tid + it * 256;
        int n = idx >> 5, c = idx & 31;
        cp16(sb + (uint32_t)(VS_OFF + buf * VBUF + n * VPAD + 4 * c) * 4u,
             vg + (size_t)n * DH + 4 * c);
    }
}

__global__ void __launch_bounds__(256, 2)
fa_tf32_kernel(const float* __restrict__ mask, float* __restrict__ out) {
    extern __shared__ float smem[];
    const uint32_t sb = smem_u32(smem);

    const int tid  = threadIdx.x;
    const int w    = tid >> 5;
    const int lane = tid & 31;
    const int g    = lane >> 2;
    const int tg   = lane & 3;

    const int qt = blockIdx.x;
    const int bh = blockIdx.y;
    const int q0 = qt * BQ;
    const size_t base = (size_t)bh * SEQ * DH;
    float* Ls = smem + L_OFF;

    // ---- producer state ----
    uint32_t qa[16][4];
    float lrow0 = 0.f, lrow1 = 0.f;
    const float* mk0 = 0; const float* mk1 = 0;
    if (w < 4) {
        const float* qp = g_Qs + base + (size_t)(q0 + w * 16) * DH;
#pragma unroll
        for (int s = 0; s < 16; s++) {
            qa[s][0] = __float_as_uint(qp[(size_t)g       * DH + 8 * s + tg    ]);
            qa[s][1] = __float_as_uint(qp[(size_t)(g + 8) * DH + 8 * s + tg    ]);
            qa[s][2] = __float_as_uint(qp[(size_t)g       * DH + 8 * s + tg + 4]);
            qa[s][3] = __float_as_uint(qp[(size_t)(g + 8) * DH + 8 * s + tg + 4]);
        }
        mk0 = mask + (size_t)(q0 + w * 16 + g)     * SEQ;
        mk1 = mask + (size_t)(q0 + w * 16 + g + 8) * SEQ;
    }
    // ---- consumer state ----
    float oacc[16][4];
    if (w >= 4) {
#pragma unroll
        for (int d = 0; d < 16; d++) {
            oacc[d][0] = 0.f; oacc[d][1] = 0.f; oacc[d][2] = 0.f; oacc[d][3] = 0.f;
        }
    }

    load_K(sb, tid, base, 0, 0);
    CP_COMMIT();

    for (int kt = 0; kt <= NKT; kt++) {
        const int cur = kt & 1, nxt = cur ^ 1;
        __syncthreads();                    // buffers from iter kt-1 free to overwrite
        if (kt < NKT) {
            if (kt + 1 < NKT) load_K(sb, tid, base, kt + 1, nxt);
            load_V(sb, tid, base, kt, cur);
            CP_COMMIT();
            CP_WAIT1();                     // group kt-1 done: K(kt), V(kt-1) ready
        } else {
            CP_WAIT0();                     // V(NKT-1) ready
        }
        __syncthreads();

        if (w < 4) {
            if (kt < NKT) {
                const float* Ks = smem + KS_OFF + cur * KBUF;
                float* Ps = smem + PS_OFF + cur * PBUF + w * (16 * PPAD);
                float sacc[4][4];
#pragma unroll
                for (int nb = 0; nb < 4; nb++) {
                    sacc[nb][0] = 0.f; sacc[nb][1] = 0.f; sacc[nb][2] = 0.f; sacc[nb][3] = 0.f;
                }
#pragma unroll
                for (int s = 0; s < 16; s++) {
#pragma unroll
                    for (int nb = 0; nb < 4; nb++) {
                        const float* kr = Ks + (8 * nb + g) * KPAD + 8 * s + tg;
                        uint32_t b0 = __float_as_uint(kr[0]);
                        uint32_t b1 = __float_as_uint(kr[4]);
                        mma_tf32(sacc[nb], qa[s][0], qa[s][1], qa[s][2], qa[s][3], b0, b1);
                    }
                }
                const float* mt0 = mk0 + kt * BK;
                const float* mt1 = mk1 + kt * BK;
#pragma unroll
                for (int nb = 0; nb < 4; nb++) {
                    float2 m0 = *(const float2*)(mt0 + 8 * nb + 2 * tg);
                    float2 m1 = *(const float2*)(mt1 + 8 * nb + 2 * tg);
                    float p0 = __expf(sacc[nb][0] + m0.x);
                    float p1 = __expf(sacc[nb][1] + m0.y);
                    float p2 = __expf(sacc[nb][2] + m1.x);
                    float p3 = __expf(sacc[nb][3] + m1.y);
                    lrow0 += p0 + p1;
                    lrow1 += p2 + p3;
                    *(float2*)(Ps + g * PPAD + 8 * nb + 2 * tg)       = make_float2(tf32r(p0), tf32r(p1));
                    *(float2*)(Ps + (g + 8) * PPAD + 8 * nb + 2 * tg) = make_float2(tf32r(p2), tf32r(p3));
                }
            }
        } else {
            if (kt > 0) {
                const int c = w - 4;
                const float* Ps = smem + PS_OFF + nxt * PBUF + c * (16 * PPAD);
                const float* Vs = smem + VS_OFF + nxt * VBUF;
#pragma unroll
                for (int kb = 0; kb < 4; kb++) {
                    uint32_t a0 = __float_as_uint(Ps[g * PPAD + 8 * kb + tg]);
                    uint32_t a1 = __float_as_uint(Ps[(g + 8) * PPAD + 8 * kb + tg]);
                    uint32_t a2 = __float_as_uint(Ps[g * PPAD + 8 * kb + tg + 4]);
                    uint32_t a3 = __float_as_uint(Ps[(g + 8) * PPAD + 8 * kb + tg + 4]);
#pragma unroll
                    for (int db = 0; db < 16; db++) {
                        uint32_t b0 = __float_as_uint(Vs[(8 * kb + tg)     * VPAD + 8 * db + g]);
                        uint32_t b1 = __float_as_uint(Vs[(8 * kb + tg + 4) * VPAD + 8 * db + g]);
                        mma_tf32(oacc[db], a0, a1, a2, a3, b0, b1);
                    }
                }
            }
        }
    }

    // ---- epilogue ----
    if (w < 4) {
        lrow0 += __shfl_xor_sync(0xffffffffu, lrow0, 1);
        lrow0 += __shfl_xor_sync(0xffffffffu, lrow0, 2);
        lrow1 += __shfl_xor_sync(0xffffffffu, lrow1, 1);
        lrow1 += __shfl_xor_sync(0xffffffffu, lrow1, 2);
        if (tg == 0) {
            Ls[w * 16 + g]     = lrow0;
            Ls[w * 16 + g + 8] = lrow1;
        }
    }
    __syncthreads();
    if (w >= 4) {
        const int c = w - 4;
        float inv0 = 1.0f / Ls[c * 16 + g];
        float inv1 = 1.0f / Ls[c * 16 + g + 8];
        float* op = out + base + (size_t)(q0 + c * 16) * DH;
#pragma unroll
        for (int db = 0; db < 16; db++) {
            int col = 8 * db + 2 * tg;
            *(float2*)(op + (size_t)g       * DH + col) = make_float2(oacc[db][0] * inv0, oacc[db][1] * inv0);
            *(float2*)(op + (size_t)(g + 8) * DH + col) = make_float2(oacc[db][2] * inv1, oacc[db][3] * inv1);
        }
    }
}

extern "C" void kernel_launch(void* const* d_in, const int* in_sizes, int n_in,
                              void* d_out, int out_size) {
    const float* q    = (const float*)d_in[0];
    const float* k    = (const float*)d_in[1];
    const float* v    = (const float*)d_in[2];
    const float* mask = (const float*)d_in[3];
    float* out = (float*)d_out;

    prep_all<<<(size_t)NBH * SEQ * DH / 4 / 256, 256>>>(q, k, v);

    cudaFuncSetAttribute(fa_tf32_kernel,
                         cudaFuncAttributeMaxDynamicSharedMemorySize, SMEM_BYTES);
    cudaFuncSetAttribute(fa_tf32_kernel,
                         cudaFuncAttributePreferredSharedMemoryCarveout, 100);

    dim3 grid(SEQ / BQ, NBH);   // (32, 64)
    fa_tf32_kernel<<<grid, 256, SMEM_BYTES>>>(mask, out);
}

// round 9
// speedup vs baseline: 1.4045x; 1.4045x over previous
#include <cuda_runtime.h>
#include <cstdint>

#define SEQ   2048
#define DH    128
#define BQ    128
#define BK    64
#define NBH   64
#define NKT   (SEQ / BK)
#define KPAD  132
#define VPAD  136
#define PPAD  68
#define KBUF  (64 * KPAD)
#define VBUF  (64 * VPAD)
#define KS_OFF 0
#define VS_OFF (2 * KBUF)
#define PS_OFF (VS_OFF + 2 * VBUF)
#define SMEM_FLOATS (PS_OFF + 8 * 16 * PPAD)
#define SMEM_BYTES (SMEM_FLOATS * 4)    // 172032 B

__device__ float g_Qs[(size_t)NBH * SEQ * DH];   // tf32, pre-scaled
__device__ float g_Kr[(size_t)NBH * SEQ * DH];   // tf32
__device__ float g_Vr[(size_t)NBH * SEQ * DH];   // tf32

__device__ __forceinline__ float tf32r(float x) {
    uint32_t u; asm("cvt.rna.tf32.f32 %0, %1;" : "=r"(u) : "f"(x));
    return __uint_as_float(u);
}
__device__ __forceinline__ uint32_t smem_u32(const void* p) {
    uint32_t a;
    asm("{ .reg .u64 t; cvta.to.shared.u64 t, %1; cvt.u32.u64 %0, t; }" : "=r"(a) : "l"(p));
    return a;
}
__device__ __forceinline__ void cp16(uint32_t dst, const void* src) {
    asm volatile("cp.async.cg.shared.global [%0], [%1], 16;" :: "r"(dst), "l"(src) : "memory");
}
#define CP_COMMIT() asm volatile("cp.async.commit_group;" ::: "memory")
#define CP_WAIT1()  asm volatile("cp.async.wait_group 1;" ::: "memory")

__device__ __forceinline__ void mma_tf32(float c[4],
                                         uint32_t a0, uint32_t a1, uint32_t a2, uint32_t a3,
                                         uint32_t b0, uint32_t b1) {
    asm volatile(
        "mma.sync.aligned.m16n8k8.row.col.f32.tf32.tf32.f32 "
        "{%0,%1,%2,%3}, {%4,%5,%6,%7}, {%8,%9}, {%0,%1,%2,%3};"
        : "+f"(c[0]), "+f"(c[1]), "+f"(c[2]), "+f"(c[3])
        : "r"(a0), "r"(a1), "r"(a2), "r"(a3), "r"(b0), "r"(b1));
}

__global__ void prep_all(const float* __restrict__ q, const float* __restrict__ k,
                         const float* __restrict__ v) {
    const float sc = 0.08838834764831845f;   // 1/sqrt(128)
    size_t i = (size_t)blockIdx.x * blockDim.x + threadIdx.x;
    float4 a = ((const float4*)q)[i];
    float4 b = ((const float4*)k)[i];
    float4 c = ((const float4*)v)[i];
    a.x = tf32r(a.x * sc); a.y = tf32r(a.y * sc); a.z = tf32r(a.z * sc); a.w = tf32r(a.w * sc);
    b.x = tf32r(b.x); b.y = tf32r(b.y); b.z = tf32r(b.z); b.w = tf32r(b.w);
    c.x = tf32r(c.x); c.y = tf32r(c.y); c.z = tf32r(c.z); c.w = tf32r(c.w);
    ((float4*)g_Qs)[i] = a;
    ((float4*)g_Kr)[i] = b;
    ((float4*)g_Vr)[i] = c;
}

__device__ __forceinline__ void load_kv(uint32_t sb, int tid, size_t base, int kt, int buf) {
    const float* kg = g_Kr + base + (size_t)kt * BK * DH;
    const float* vg = g_Vr + base + (size_t)kt * BK * DH;
#pragma unroll
    for (int it = 0; it < 8; it++) {
        int idx = tid + it * 256;
        int n = idx >> 5, c = idx & 31;
        cp16(sb + (uint32_t)(KS_OFF + buf * KBUF + n * KPAD + 4 * c) * 4u, kg + (size_t)n * DH + 4 * c);
        cp16(sb + (uint32_t)(VS_OFF + buf * VBUF + n * VPAD + 4 * c) * 4u, vg + (size_t)n * DH + 4 * c);
    }
}

__global__ void __launch_bounds__(256, 1)
fa_tf32_kernel(const float* __restrict__ mask, float* __restrict__ out) {
    extern __shared__ float smem[];
    const uint32_t sb = smem_u32(smem);

    const int tid  = threadIdx.x;
    const int warp = tid >> 5;
    const int lane = tid & 31;
    const int g    = lane >> 2;
    const int tg   = lane & 3;

    float* Ps = smem + PS_OFF + warp * (16 * PPAD);

    const int qt = blockIdx.x;
    const int bh = blockIdx.y;
    const int q0 = qt * BQ;
    const size_t base = (size_t)bh * SEQ * DH;

    const float* qp = g_Qs + base + (size_t)(q0 + warp * 16) * DH;
    uint32_t qa[16][4];
#pragma unroll
    for (int s = 0; s < 16; s++) {
        qa[s][0] = __float_as_uint(qp[(size_t)g       * DH + 8 * s + tg    ]);
        qa[s][1] = __float_as_uint(qp[(size_t)(g + 8) * DH + 8 * s + tg    ]);
        qa[s][2] = __float_as_uint(qp[(size_t)g       * DH + 8 * s + tg + 4]);
        qa[s][3] = __float_as_uint(qp[(size_t)(g + 8) * DH + 8 * s + tg + 4]);
    }

    float oacc[16][4];
#pragma unroll
    for (int d = 0; d < 16; d++) {
        oacc[d][0] = 0.f; oacc[d][1] = 0.f; oacc[d][2] = 0.f; oacc[d][3] = 0.f;
    }
    float lrow0 = 0.f, lrow1 = 0.f;

    const float* mk0 = mask + (size_t)(q0 + warp * 16 + g)     * SEQ;
    const float* mk1 = mask + (size_t)(q0 + warp * 16 + g + 8) * SEQ;

    load_kv(sb, tid, base, 0, 0);
    CP_COMMIT();

    for (int kt = 0; kt < NKT; kt++) {
        const int cur = kt & 1, nxt = cur ^ 1;
        __syncthreads();
        if (kt + 1 < NKT) load_kv(sb, tid, base, kt + 1, nxt);
        CP_COMMIT();
        CP_WAIT1();
        __syncthreads();

        const float* Ks = smem + KS_OFF + cur * KBUF;
        const float* Vs = smem + VS_OFF + cur * VBUF;

        // ---- hoist ALL mask loads before the MMA block: LDGs fly during QK ----
        const float* mt0 = mk0 + kt * BK;
        const float* mt1 = mk1 + kt * BK;
        float2 mreg0[8], mreg1[8];
#pragma unroll
        for (int nb = 0; nb < 8; nb++) {
            mreg0[nb] = *(const float2*)(mt0 + 8 * nb + 2 * tg);
            mreg1[nb] = *(const float2*)(mt1 + 8 * nb + 2 * tg);
        }

        // ---- S = Q K^T (16x64 per warp) ----
        float sacc[8][4];
#pragma unroll
        for (int nb = 0; nb < 8; nb++) {
            sacc[nb][0] = 0.f; sacc[nb][1] = 0.f; sacc[nb][2] = 0.f; sacc[nb][3] = 0.f;
        }
#pragma unroll
        for (int s = 0; s < 16; s++) {
#pragma unroll
            for (int nb = 0; nb < 8; nb++) {
                const float* kr = Ks + (8 * nb + g) * KPAD + 8 * s + tg;
                uint32_t b0 = __float_as_uint(kr[0]);
                uint32_t b1 = __float_as_uint(kr[4]);
                mma_tf32(sacc[nb], qa[s][0], qa[s][1], qa[s][2], qa[s][3], b0, b1);
            }
        }

        // ---- mask (from regs) + exp, P -> smem ----
#pragma unroll
        for (int nb = 0; nb < 8; nb++) {
            float p0 = __expf(sacc[nb][0] + mreg0[nb].x);
            float p1 = __expf(sacc[nb][1] + mreg0[nb].y);
            float p2 = __expf(sacc[nb][2] + mreg1[nb].x);
            float p3 = __expf(sacc[nb][3] + mreg1[nb].y);
            lrow0 += p0 + p1;
            lrow1 += p2 + p3;
            *(float2*)(Ps + g * PPAD + 8 * nb + 2 * tg)       = make_float2(tf32r(p0), tf32r(p1));
            *(float2*)(Ps + (g + 8) * PPAD + 8 * nb + 2 * tg) = make_float2(tf32r(p2), tf32r(p3));
        }
        __syncwarp();

        // ---- O += P V ----
#pragma unroll
        for (int kb = 0; kb < 8; kb++) {
            uint32_t a0 = __float_as_uint(Ps[g * PPAD + 8 * kb + tg]);
            uint32_t a1 = __float_as_uint(Ps[(g + 8) * PPAD + 8 * kb + tg]);
            uint32_t a2 = __float_as_uint(Ps[g * PPAD + 8 * kb + tg + 4]);
            uint32_t a3 = __float_as_uint(Ps[(g + 8) * PPAD + 8 * kb + tg + 4]);
#pragma unroll
            for (int db = 0; db < 16; db++) {
                uint32_t b0 = __float_as_uint(Vs[(8 * kb + tg)     * VPAD + 8 * db + g]);
                uint32_t b1 = __float_as_uint(Vs[(8 * kb + tg + 4) * VPAD + 8 * db + g]);
                mma_tf32(oacc[db], a0, a1, a2, a3, b0, b1);
            }
        }
    }

    // ---- epilogue ----
    lrow0 += __shfl_xor_sync(0xffffffffu, lrow0, 1);
    lrow0 += __shfl_xor_sync(0xffffffffu, lrow0, 2);
    lrow1 += __shfl_xor_sync(0xffffffffu, lrow1, 1);
    lrow1 += __shfl_xor_sync(0xffffffffu, lrow1, 2);
    float inv0 = 1.0f / lrow0;
    float inv1 = 1.0f / lrow1;
    float* op = out + base + (size_t)(q0 + warp * 16) * DH;
#pragma unroll
    for (int db = 0; db < 16; db++) {
        int c = 8 * db + 2 * tg;
        *(float2*)(op + (size_t)g       * DH + c) = make_float2(oacc[db][0] * inv0, oacc[db][1] * inv0);
        *(float2*)(op + (size_t)(g + 8) * DH + c) = make_float2(oacc[db][2] * inv1, oacc[db][3] * inv1);
    }
}

extern "C" void kernel_launch(void* const* d_in, const int* in_sizes, int n_in,
                              void* d_out, int out_size) {
    const float* q    = (const float*)d_in[0];
    const float* k    = (const float*)d_in[1];
    const float* v    = (const float*)d_in[2];
    const float* mask = (const float*)d_in[3];
    float* out = (float*)d_out;

    prep_all<<<(size_t)NBH * SEQ * DH / 4 / 256, 256>>>(q, k, v);

    cudaFuncSetAttribute(fa_tf32_kernel,
                         cudaFuncAttributeMaxDynamicSharedMemorySize, SMEM_BYTES);
    cudaFuncSetAttribute(fa_tf32_kernel,
                         cudaFuncAttributePreferredSharedMemoryCarveout, 100);

    dim3 grid(SEQ / BQ, NBH);   // (16, 64)
    fa_tf32_kernel<<<grid, 256, SMEM_BYTES>>>(mask, out);
}